// round 1
// baseline (speedup 1.0000x reference)
#include <cuda_runtime.h>
#include <cstdint>

#define OUTP 7
#define SRR 2
#define RBOX 256
#define CCH 256
#define NSAMP (OUTP * SRR)   // 14 sample coords per axis
#define BINS (OUTP * OUTP)   // 49
#define OUT_PER_BOX (CCH * BINS)  // 12544

__global__ __launch_bounds__(256) void roi_pooler_kernel(
    const float* __restrict__ f0, const float* __restrict__ f1,
    const float* __restrict__ f2, const float* __restrict__ f3,
    const float* __restrict__ boxes, float* __restrict__ out)
{
    // Per-box precomputed sample data
    __shared__ int   s_offlo_y[NSAMP], s_offhi_y[NSAMP];   // row offsets (already *W)
    __shared__ float s_wy0[NSAMP], s_wy1[NSAMP];           // (1-fy)*vy, fy*vy
    __shared__ int   s_xlo[NSAMP], s_xhi[NSAMP];
    __shared__ float s_wx0[NSAMP], s_wx1[NSAMP];           // (1-fx)*vx, fx*vx
    __shared__ float s_y1, s_x1, s_bh, s_bw, s_Hf, s_Wf;
    __shared__ int   s_W, s_HW;
    __shared__ const float* s_base;

    const int n   = blockIdx.x;      // box index in [0, 512)
    const int tid = threadIdx.x;

    if (tid == 0) {
        const int b = n >> 8;        // n / RBOX
        const float bx1 = boxes[n * 4 + 0];
        const float by1 = boxes[n * 4 + 1];
        const float bx2 = boxes[n * 4 + 2];
        const float by2 = boxes[n * 4 + 3];
        const float area = (bx2 - bx1) * (by2 - by1);
        // lvl = clip(floor(4 + log2(sqrt(area)/224 + 1e-8)), 2, 5) - 2
        float lvlf = floorf(4.0f + log2f(sqrtf(area) * (1.0f / 224.0f) + 1e-8f));
        lvlf = fminf(fmaxf(lvlf, 2.0f), 5.0f);
        const int lvl = (int)lvlf - 2;

        int H, W;
        float scale;
        const float* fp;
        switch (lvl) {
            case 0:  H = 200; W = 200; scale = 0.25f;    fp = f0; break;
            case 1:  H = 100; W = 100; scale = 0.125f;   fp = f1; break;
            case 2:  H = 50;  W = 50;  scale = 0.0625f;  fp = f2; break;
            default: H = 25;  W = 25;  scale = 0.03125f; fp = f3; break;
        }
        const float x1s = bx1 * scale;
        const float y1s = by1 * scale;
        const float x2s = bx2 * scale;
        const float y2s = by2 * scale;
        const float roi_w = fmaxf(x2s - x1s, 1.0f);
        const float roi_h = fmaxf(y2s - y1s, 1.0f);

        s_x1 = x1s;  s_y1 = y1s;
        s_bw = roi_w * (1.0f / OUTP);
        s_bh = roi_h * (1.0f / OUTP);
        s_Hf = (float)H;  s_Wf = (float)W;
        s_W  = W;         s_HW = H * W;
        s_base = fp + (size_t)b * CCH * H * W;
    }
    __syncthreads();

    // Sample-point prep: 14 y-samples + 14 x-samples (torchvision aligned=False)
    if (tid < 2 * NSAMP) {
        const bool is_y = tid < NSAMP;
        const int  i    = is_y ? tid : tid - NSAMP;
        const int  p    = i >> 1;          // bin index along this axis
        const int  s    = i & 1;           // sub-sample index
        const float g   = (float)p + ((float)s + 0.5f) * 0.5f;
        const float coord = is_y ? (s_y1 + s_bh * g) : (s_x1 + s_bw * g);
        const float lim   = is_y ? s_Hf : s_Wf;

        const float v  = (coord > -1.0f && coord < lim) ? 1.0f : 0.0f;
        float cc  = fmaxf(coord, 0.0f);
        float low = floorf(cc);
        const float cap = lim - 1.0f;
        const bool at_edge = (low >= cap);
        low = fminf(low, cap);
        const float high = fminf(low + 1.0f, cap);
        if (at_edge) cc = low;
        const float frac = cc - low;
        const float w0 = (1.0f - frac) * v;
        const float w1 = frac * v;

        if (is_y) {
            const int W = s_W;
            s_offlo_y[i] = (int)low * W;
            s_offhi_y[i] = (int)high * W;
            s_wy0[i] = w0;
            s_wy1[i] = w1;
        } else {
            s_xlo[i] = (int)low;
            s_xhi[i] = (int)high;
            s_wx0[i] = w0;
            s_wx1[i] = w1;
        }
    }
    __syncthreads();

    const float* const base = s_base;
    const int HW = s_HW;
    float* const out_n = out + (size_t)n * OUT_PER_BOX;

    // 12544 outputs per box, 256 threads -> 49 iterations
    #pragma unroll 1
    for (int it = 0; it < BINS; ++it) {
        const unsigned idx = (unsigned)(it * 256 + tid);
        const unsigned c   = idx / BINS;          // mul-shift
        const unsigned bin = idx - c * BINS;
        const unsigned ph  = bin / OUTP;
        const unsigned pw  = bin - ph * OUTP;

        const float* const bp = base + (size_t)c * HW;
        float acc = 0.0f;

        #pragma unroll
        for (int sy = 0; sy < 2; ++sy) {
            const int iy = (int)(ph * 2) + sy;
            const int ol = s_offlo_y[iy];
            const int oh = s_offhi_y[iy];
            const float wy0 = s_wy0[iy];
            const float wy1 = s_wy1[iy];
            #pragma unroll
            for (int sx = 0; sx < 2; ++sx) {
                const int ix = (int)(pw * 2) + sx;
                const int xl = s_xlo[ix];
                const int xh = s_xhi[ix];
                const float wx0 = s_wx0[ix];
                const float wx1 = s_wx1[ix];
                const float v00 = bp[ol + xl];
                const float v01 = bp[ol + xh];
                const float v10 = bp[oh + xl];
                const float v11 = bp[oh + xh];
                const float t0 = wx0 * v00 + wx1 * v01;
                const float t1 = wx0 * v10 + wx1 * v11;
                acc += wy0 * t0 + wy1 * t1;
            }
        }
        out_n[idx] = acc * 0.25f;
    }
}

extern "C" void kernel_launch(void* const* d_in, const int* in_sizes, int n_in,
                              void* d_out, int out_size) {
    const float* f0    = (const float*)d_in[0];
    const float* f1    = (const float*)d_in[1];
    const float* f2    = (const float*)d_in[2];
    const float* f3    = (const float*)d_in[3];
    const float* boxes = (const float*)d_in[4];
    float* out = (float*)d_out;

    roi_pooler_kernel<<<512, 256>>>(f0, f1, f2, f3, boxes, out);
}

// round 2
// speedup vs baseline: 1.5046x; 1.5046x over previous
#include <cuda_runtime.h>
#include <cstdint>

#define OUTP 7
#define SRR 2
#define RBOX 256
#define CCH 256
#define NSAMP (OUTP * SRR)        // 14 sample coords per axis
#define BINS (OUTP * OUTP)        // 49
#define OUT_PER_BOX (CCH * BINS)  // 12544
#define CGROUPS 4
#define CH_PER_GROUP (CCH / CGROUPS)          // 64
#define OUT_PER_GROUP (CH_PER_GROUP * BINS)   // 3136
#define THREADS 448                            // 3136 / 448 = 7 exact

__global__ __launch_bounds__(THREADS) void roi_pooler_kernel(
    const float* __restrict__ f0, const float* __restrict__ f1,
    const float* __restrict__ f2, const float* __restrict__ f3,
    const float* __restrict__ boxes, float* __restrict__ out)
{
    // Per-box precomputed sample data
    __shared__ int   s_offlo_y[NSAMP], s_offhi_y[NSAMP];   // row offsets (already *W)
    __shared__ float s_wy0[NSAMP], s_wy1[NSAMP];           // (1-fy)*vy, fy*vy
    __shared__ int   s_xlo[NSAMP], s_xhi[NSAMP];
    __shared__ float s_wx0[NSAMP], s_wx1[NSAMP];           // (1-fx)*vx, fx*vx
    __shared__ float s_y1, s_x1, s_bh, s_bw, s_Hf, s_Wf;
    __shared__ int   s_W, s_HW;
    __shared__ const float* s_base;

    const int blk = blockIdx.x;          // [0, 512*CGROUPS)
    const int n   = blk >> 2;            // box index [0,512)
    const int g   = blk & 3;             // channel group [0,4)
    const int tid = threadIdx.x;

    if (tid == 0) {
        const int b = n >> 8;            // n / RBOX
        const float bx1 = boxes[n * 4 + 0];
        const float by1 = boxes[n * 4 + 1];
        const float bx2 = boxes[n * 4 + 2];
        const float by2 = boxes[n * 4 + 3];
        const float area = (bx2 - bx1) * (by2 - by1);
        // lvl = clip(floor(4 + log2(sqrt(area)/224 + 1e-8)), 2, 5) - 2
        float lvlf = floorf(4.0f + log2f(sqrtf(area) * (1.0f / 224.0f) + 1e-8f));
        lvlf = fminf(fmaxf(lvlf, 2.0f), 5.0f);
        const int lvl = (int)lvlf - 2;

        int H, W;
        float scale;
        const float* fp;
        switch (lvl) {
            case 0:  H = 200; W = 200; scale = 0.25f;    fp = f0; break;
            case 1:  H = 100; W = 100; scale = 0.125f;   fp = f1; break;
            case 2:  H = 50;  W = 50;  scale = 0.0625f;  fp = f2; break;
            default: H = 25;  W = 25;  scale = 0.03125f; fp = f3; break;
        }
        const float x1s = bx1 * scale;
        const float y1s = by1 * scale;
        const float x2s = bx2 * scale;
        const float y2s = by2 * scale;
        const float roi_w = fmaxf(x2s - x1s, 1.0f);
        const float roi_h = fmaxf(y2s - y1s, 1.0f);

        s_x1 = x1s;  s_y1 = y1s;
        s_bw = roi_w * (1.0f / OUTP);
        s_bh = roi_h * (1.0f / OUTP);
        s_Hf = (float)H;  s_Wf = (float)W;
        s_W  = W;         s_HW = H * W;
        // base for this box AND this channel group
        s_base = fp + ((size_t)b * CCH + (size_t)g * CH_PER_GROUP) * H * W;
    }
    __syncthreads();

    // Sample-point prep: 14 y-samples + 14 x-samples (torchvision aligned=False)
    if (tid < 2 * NSAMP) {
        const bool is_y = tid < NSAMP;
        const int  i    = is_y ? tid : tid - NSAMP;
        const int  p    = i >> 1;          // bin index along this axis
        const int  s    = i & 1;           // sub-sample index
        const float gg  = (float)p + ((float)s + 0.5f) * 0.5f;
        const float coord = is_y ? (s_y1 + s_bh * gg) : (s_x1 + s_bw * gg);
        const float lim   = is_y ? s_Hf : s_Wf;

        const float v  = (coord > -1.0f && coord < lim) ? 1.0f : 0.0f;
        float cc  = fmaxf(coord, 0.0f);
        float low = floorf(cc);
        const float cap = lim - 1.0f;
        const bool at_edge = (low >= cap);
        low = fminf(low, cap);
        const float high = fminf(low + 1.0f, cap);
        if (at_edge) cc = low;
        const float frac = cc - low;
        const float w0 = (1.0f - frac) * v;
        const float w1 = frac * v;

        if (is_y) {
            const int W = s_W;
            s_offlo_y[i] = (int)low * W;
            s_offhi_y[i] = (int)high * W;
            s_wy0[i] = w0;
            s_wy1[i] = w1;
        } else {
            s_xlo[i] = (int)low;
            s_xhi[i] = (int)high;
            s_wx0[i] = w0;
            s_wx1[i] = w1;
        }
    }
    __syncthreads();

    const float* const base = s_base;
    const int HW = s_HW;
    float* const out_g = out + (size_t)n * OUT_PER_BOX + (size_t)g * OUT_PER_GROUP;

    // 3136 outputs per (box, group), 448 threads -> exactly 7 iterations
    #pragma unroll 1
    for (int it = 0; it < OUT_PER_GROUP / THREADS; ++it) {
        const unsigned idx = (unsigned)(it * THREADS + tid);
        const unsigned c   = idx / BINS;          // local channel within group
        const unsigned bin = idx - c * BINS;
        const unsigned ph  = bin / OUTP;
        const unsigned pw  = bin - ph * OUTP;

        const float* const bp = base + (size_t)c * HW;
        float acc = 0.0f;

        #pragma unroll
        for (int sy = 0; sy < 2; ++sy) {
            const int iy = (int)(ph * 2) + sy;
            const int ol = s_offlo_y[iy];
            const int oh = s_offhi_y[iy];
            const float wy0 = s_wy0[iy];
            const float wy1 = s_wy1[iy];
            #pragma unroll
            for (int sx = 0; sx < 2; ++sx) {
                const int ix = (int)(pw * 2) + sx;
                const int xl = s_xlo[ix];
                const int xh = s_xhi[ix];
                const float wx0 = s_wx0[ix];
                const float wx1 = s_wx1[ix];
                const float v00 = bp[ol + xl];
                const float v01 = bp[ol + xh];
                const float v10 = bp[oh + xl];
                const float v11 = bp[oh + xh];
                const float t0 = wx0 * v00 + wx1 * v01;
                const float t1 = wx0 * v10 + wx1 * v11;
                acc += wy0 * t0 + wy1 * t1;
            }
        }
        out_g[idx] = acc * 0.25f;
    }
}

extern "C" void kernel_launch(void* const* d_in, const int* in_sizes, int n_in,
                              void* d_out, int out_size) {
    const float* f0    = (const float*)d_in[0];
    const float* f1    = (const float*)d_in[1];
    const float* f2    = (const float*)d_in[2];
    const float* f3    = (const float*)d_in[3];
    const float* boxes = (const float*)d_in[4];
    float* out = (float*)d_out;

    roi_pooler_kernel<<<512 * CGROUPS, THREADS>>>(f0, f1, f2, f3, boxes, out);
}

// round 3
// speedup vs baseline: 1.5516x; 1.0312x over previous
#include <cuda_runtime.h>
#include <cstdint>

#define OUTP 7
#define CCH 256
#define NSAMP 14                     // sample coords per axis (7 bins * 2 subsamples)
#define BINS (OUTP * OUTP)           // 49
#define OUT_PER_BOX (CCH * BINS)     // 12544
#define CH_PER_CTA 32
#define NGROUPS (CCH / CH_PER_CTA)   // 8
#define THREADS 256
#define NWARPS (THREADS / 32)        // 8
#define TASKS_PER_CTA (CH_PER_CTA * OUTP)      // 224  (channel, bin-row) tasks
#define TASKS_PER_WARP (TASKS_PER_CTA / NWARPS) // 28

__global__ __launch_bounds__(THREADS) void roi_pooler_kernel(
    const float* __restrict__ f0, const float* __restrict__ f1,
    const float* __restrict__ f2, const float* __restrict__ f3,
    const float* __restrict__ boxes, float* __restrict__ out)
{
    // Per-box precomputed taps/weights (validity folded into weights)
    __shared__ float s_wy0[NSAMP], s_wy1[NSAMP];   // per y-sample iy: (1-fy)*vy, fy*vy
    __shared__ int   s_rowoff[2 * NSAMP];          // row taps: [2i]=yl(i)*W, [2i+1]=yh(i)*W
    __shared__ int   s_col[2 * NSAMP];             // col taps: [2i]=xl(i), [2i+1]=xh(i)
    __shared__ float s_wxw[2 * NSAMP];             // per col tap: [2i]=(1-fx)*vx, [2i+1]=fx*vx
    __shared__ float s_y1, s_x1, s_bh, s_bw, s_Hf, s_Wf;
    __shared__ int   s_W, s_HW;
    __shared__ const float* s_base;

    const int blk = blockIdx.x;           // [0, 512*NGROUPS)
    const int n   = blk >> 3;             // box index [0,512)
    const int g   = blk & (NGROUPS - 1);  // channel group [0,8)
    const int tid = threadIdx.x;

    if (tid == 0) {
        const int b = n >> 8;             // n / 256 boxes-per-batch
        const float bx1 = boxes[n * 4 + 0];
        const float by1 = boxes[n * 4 + 1];
        const float bx2 = boxes[n * 4 + 2];
        const float by2 = boxes[n * 4 + 3];
        const float area = (bx2 - bx1) * (by2 - by1);
        float lvlf = floorf(4.0f + log2f(sqrtf(area) * (1.0f / 224.0f) + 1e-8f));
        lvlf = fminf(fmaxf(lvlf, 2.0f), 5.0f);
        const int lvl = (int)lvlf - 2;

        int H, W;
        float scale;
        const float* fp;
        switch (lvl) {
            case 0:  H = 200; W = 200; scale = 0.25f;    fp = f0; break;
            case 1:  H = 100; W = 100; scale = 0.125f;   fp = f1; break;
            case 2:  H = 50;  W = 50;  scale = 0.0625f;  fp = f2; break;
            default: H = 25;  W = 25;  scale = 0.03125f; fp = f3; break;
        }
        const float x1s = bx1 * scale;
        const float y1s = by1 * scale;
        const float x2s = bx2 * scale;
        const float y2s = by2 * scale;
        const float roi_w = fmaxf(x2s - x1s, 1.0f);
        const float roi_h = fmaxf(y2s - y1s, 1.0f);

        s_x1 = x1s;  s_y1 = y1s;
        s_bw = roi_w * (1.0f / OUTP);
        s_bh = roi_h * (1.0f / OUTP);
        s_Hf = (float)H;  s_Wf = (float)W;
        s_W  = W;         s_HW = H * W;
        s_base = fp + ((size_t)b * CCH + (size_t)g * CH_PER_CTA) * H * W;
    }
    __syncthreads();

    // Sample prep (torchvision ROIAlign aligned=False)
    if (tid < 2 * NSAMP) {
        const bool is_y = tid < NSAMP;
        const int  i    = is_y ? tid : tid - NSAMP;
        const int  p    = i >> 1;
        const int  s    = i & 1;
        const float gg  = (float)p + ((float)s + 0.5f) * 0.5f;
        const float coord = is_y ? (s_y1 + s_bh * gg) : (s_x1 + s_bw * gg);
        const float lim   = is_y ? s_Hf : s_Wf;

        const float v  = (coord > -1.0f && coord < lim) ? 1.0f : 0.0f;
        float cc  = fmaxf(coord, 0.0f);
        float low = floorf(cc);
        const float cap = lim - 1.0f;
        const bool at_edge = (low >= cap);
        low = fminf(low, cap);
        const float high = fminf(low + 1.0f, cap);
        if (at_edge) cc = low;
        const float frac = cc - low;
        const float w0 = (1.0f - frac) * v;
        const float w1 = frac * v;

        if (is_y) {
            const int W = s_W;
            s_rowoff[2 * i + 0] = (int)low * W;
            s_rowoff[2 * i + 1] = (int)high * W;
            s_wy0[i] = w0;
            s_wy1[i] = w1;
        } else {
            s_col[2 * i + 0] = (int)low;
            s_col[2 * i + 1] = (int)high;
            s_wxw[2 * i + 0] = w0;
            s_wxw[2 * i + 1] = w1;
        }
    }
    __syncthreads();

    const int lane = tid & 31;
    const int wid  = tid >> 5;
    const int laneT = (lane < 28) ? lane : 27;    // col tap index (lanes 28-31 duplicate)
    const int  colb = s_col[laneT];
    const float wxwb = s_wxw[laneT];

    const float* const base = s_base;
    const int HW = s_HW;
    float* const out_g = out + (size_t)n * OUT_PER_BOX + (size_t)g * CH_PER_CTA * BINS;

    const bool writer = ((lane & 3) == 0) && (lane < 28);
    const int pw = lane >> 2;

    // Each warp: 28 (channel, ph) tasks, contiguous channels
    #pragma unroll 1
    for (int k = 0; k < TASKS_PER_WARP; k += 2) {
        #pragma unroll
        for (int u = 0; u < 2; ++u) {
            const int t  = wid * TASKS_PER_WARP + k + u;
            const int ch = t / OUTP;
            const int ph = t - ch * OUTP;

            const float* const p = base + ch * HW + colb;
            const int ro0 = s_rowoff[4 * ph + 0];
            const int ro1 = s_rowoff[4 * ph + 1];
            const int ro2 = s_rowoff[4 * ph + 2];
            const int ro3 = s_rowoff[4 * ph + 3];

            const float v0 = p[ro0];
            const float v1 = p[ro1];
            const float v2 = p[ro2];
            const float v3 = p[ro3];

            const float wy00 = s_wy0[2 * ph + 0];
            const float wy01 = s_wy1[2 * ph + 0];
            const float wy10 = s_wy0[2 * ph + 1];
            const float wy11 = s_wy1[2 * ph + 1];

            const float sa = wy00 * v0 + wy01 * v1;     // sample row iy=2ph at this col tap
            const float sb = wy10 * v2 + wy11 * v3;     // sample row iy=2ph+1
            float acc = wxwb * (sa + sb);

            acc += __shfl_xor_sync(0xffffffffu, acc, 1);
            acc += __shfl_xor_sync(0xffffffffu, acc, 2);

            if (writer) {
                out_g[ch * BINS + ph * OUTP + pw] = acc * 0.25f;
            }
        }
    }
}

extern "C" void kernel_launch(void* const* d_in, const int* in_sizes, int n_in,
                              void* d_out, int out_size) {
    const float* f0    = (const float*)d_in[0];
    const float* f1    = (const float*)d_in[1];
    const float* f2    = (const float*)d_in[2];
    const float* f3    = (const float*)d_in[3];
    const float* boxes = (const float*)d_in[4];
    float* out = (float*)d_out;

    roi_pooler_kernel<<<512 * NGROUPS, THREADS>>>(f0, f1, f2, f3, boxes, out);
}